// round 2
// baseline (speedup 1.0000x reference)
#include <cuda_runtime.h>
#include <cuda_bf16.h>

#define N_NODES 50000
#define IN_CH   128
#define F1      128     // HEADS*HID
#define HEADS   4
#define HID     32
#define OUT_CH  8
#define NEG_SLOPE 0.2f

// ---------------- scratch (device globals; no allocation allowed) ----------
__device__ float g_h1 [N_NODES * F1];     // layer-1 linear output
__device__ float g_as1[N_NODES * HEADS];  // alpha_src layer 1
__device__ float g_ad1[N_NODES * HEADS];  // alpha_dst layer 1
__device__ float g_sum1[N_NODES * HEADS]; // softmax denominators layer 1
__device__ float g_out1[N_NODES * F1];    // aggregated layer-1 output (+bias)
__device__ float g_h2 [N_NODES * OUT_CH]; // layer-2 linear output
__device__ float g_as2[N_NODES];
__device__ float g_ad2[N_NODES];
__device__ float g_sum2[N_NODES];

__device__ __forceinline__ float lrelu(float x) { return x > 0.f ? x : NEG_SLOPE * x; }

// ---------------- K0: init accumulators ------------------------------------
__global__ void k_init(const float* __restrict__ b1, const float* __restrict__ b2,
                       float* __restrict__ out, int N) {
    int i = blockIdx.x * blockDim.x + threadIdx.x;
    int NF = N * F1;
    if (i < NF)          g_out1[i] = b1[i & 127];
    if (i < N * HEADS)   g_sum1[i] = 0.f;
    if (i < N)           g_sum2[i] = 0.f;
    if (i < N * OUT_CH)  out[i]    = b2[i & 7];
}

// ---------------- K1: h1 = x @ W1 ; alpha_src1/alpha_dst1 -------------------
// block: 128 threads, 16 rows per block
__global__ void k_gemm1(const float* __restrict__ x, const float* __restrict__ W1,
                        const float* __restrict__ a_src1, const float* __restrict__ a_dst1,
                        int N) {
    __shared__ float xs[16][IN_CH];
    __shared__ float hs[16][F1];
    const int t = threadIdx.x;            // output column 0..127
    const int row0 = blockIdx.x * 16;

    #pragma unroll
    for (int r = 0; r < 16; r++) {
        int n = row0 + r;
        xs[r][t] = (n < N) ? x[n * IN_CH + t] : 0.f;
    }
    __syncthreads();

    float acc[16];
    #pragma unroll
    for (int r = 0; r < 16; r++) acc[r] = 0.f;

    for (int k = 0; k < IN_CH; k++) {
        float w = W1[k * F1 + t];
        #pragma unroll
        for (int r = 0; r < 16; r++) acc[r] += xs[r][k] * w;
    }

    #pragma unroll
    for (int r = 0; r < 16; r++) {
        hs[r][t] = acc[r];
        int n = row0 + r;
        if (n < N) g_h1[n * F1 + t] = acc[r];
    }
    __syncthreads();

    // 16 rows * 4 heads * {src,dst} = 128 tasks, one per thread
    const int r    = t >> 3;
    const int q    = t & 7;
    const int head = q & 3;
    const bool is_dst = (q >= 4);
    const float* a = is_dst ? a_dst1 : a_src1;
    float s = 0.f;
    #pragma unroll
    for (int c = 0; c < HID; c++) s += hs[r][head * HID + c] * a[head * HID + c];
    int n = row0 + r;
    if (n < N) {
        if (is_dst) g_ad1[n * HEADS + head] = s;
        else        g_as1[n * HEADS + head] = s;
    }
}

// ---------------- K2: layer-1 edge pass A: softmax denominators -------------
__global__ void k_edgeA1(const int* __restrict__ ei, int E, int ET) {
    int e = blockIdx.x * blockDim.x + threadIdx.x;
    if (e >= ET) return;
    int s, d;
    if (e < E) { s = ei[e]; d = ei[E + e]; }
    else       { s = d = e - E; }
    float4 as = *(const float4*)&g_as1[s * 4];
    float4 ad = *(const float4*)&g_ad1[d * 4];
    atomicAdd(&g_sum1[d * 4 + 0], expf(lrelu(as.x + ad.x)));
    atomicAdd(&g_sum1[d * 4 + 1], expf(lrelu(as.y + ad.y)));
    atomicAdd(&g_sum1[d * 4 + 2], expf(lrelu(as.z + ad.z)));
    atomicAdd(&g_sum1[d * 4 + 3], expf(lrelu(as.w + ad.w)));
}

// ---------------- K3: layer-1 edge pass B: weighted aggregation -------------
// one warp per edge; lane handles 4 consecutive channels (same head)
__global__ void k_edgeB1(const int* __restrict__ ei, int E, int ET) {
    int gw   = (blockIdx.x * blockDim.x + threadIdx.x) >> 5;
    int lane = threadIdx.x & 31;
    if (gw >= ET) return;
    int s, d;
    if (gw < E) { s = ei[gw]; d = ei[E + gw]; }
    else        { s = d = gw - E; }
    int head = lane >> 3;
    float lo = g_as1[s * 4 + head] + g_ad1[d * 4 + head];
    float coeff = expf(lrelu(lo)) / g_sum1[d * 4 + head];
    float4 v = ((const float4*)g_h1)[s * 32 + lane];
    float* o = &g_out1[d * F1 + lane * 4];
    atomicAdd(o + 0, v.x * coeff);
    atomicAdd(o + 1, v.y * coeff);
    atomicAdd(o + 2, v.z * coeff);
    atomicAdd(o + 3, v.w * coeff);
}

// ---------------- K4: elu -> h2 = elu(out1) @ W2 ; alpha_src2/alpha_dst2 ----
// one warp per node
__global__ void k_gemm2(const float* __restrict__ W2,
                        const float* __restrict__ a_src2, const float* __restrict__ a_dst2,
                        int N) {
    __shared__ float W2s[F1 * OUT_CH];
    __shared__ float a2s[OUT_CH], a2d[OUT_CH];
    int t = threadIdx.x;
    for (int i = t; i < F1 * OUT_CH; i += blockDim.x) W2s[i] = W2[i];
    if (t < OUT_CH) { a2s[t] = a_src2[t]; a2d[t] = a_dst2[t]; }
    __syncthreads();

    int gw   = (blockIdx.x * blockDim.x + t) >> 5;
    int lane = t & 31;
    if (gw >= N) return;
    int n = gw;

    float v[4];
    #pragma unroll
    for (int j = 0; j < 4; j++) {
        float h = g_out1[n * F1 + lane * 4 + j];
        v[j] = h > 0.f ? h : expm1f(h);
    }
    float h2v[OUT_CH];
    #pragma unroll
    for (int o = 0; o < OUT_CH; o++) {
        float p = 0.f;
        #pragma unroll
        for (int j = 0; j < 4; j++) p += v[j] * W2s[(lane * 4 + j) * OUT_CH + o];
        #pragma unroll
        for (int off = 16; off; off >>= 1) p += __shfl_xor_sync(0xFFFFFFFFu, p, off);
        h2v[o] = p;
    }
    if (lane < OUT_CH) g_h2[n * OUT_CH + lane] = h2v[lane];
    if (lane == 0) {
        float s1 = 0.f, s2 = 0.f;
        #pragma unroll
        for (int o = 0; o < OUT_CH; o++) { s1 += h2v[o] * a2s[o]; s2 += h2v[o] * a2d[o]; }
        g_as2[n] = s1;
        g_ad2[n] = s2;
    }
}

// ---------------- K5: layer-2 edge pass A -----------------------------------
__global__ void k_edgeA2(const int* __restrict__ ei, int E, int ET) {
    int e = blockIdx.x * blockDim.x + threadIdx.x;
    if (e >= ET) return;
    int s, d;
    if (e < E) { s = ei[e]; d = ei[E + e]; }
    else       { s = d = e - E; }
    atomicAdd(&g_sum2[d], expf(lrelu(g_as2[s] + g_ad2[d])));
}

// ---------------- K6: layer-2 edge pass B -----------------------------------
__global__ void k_edgeB2(const int* __restrict__ ei, float* __restrict__ out,
                         int E, int ET) {
    int e = blockIdx.x * blockDim.x + threadIdx.x;
    if (e >= ET) return;
    int s, d;
    if (e < E) { s = ei[e]; d = ei[E + e]; }
    else       { s = d = e - E; }
    float coeff = expf(lrelu(g_as2[s] + g_ad2[d])) / g_sum2[d];
    float4 a = ((const float4*)g_h2)[s * 2 + 0];
    float4 b = ((const float4*)g_h2)[s * 2 + 1];
    float* o = &out[d * OUT_CH];
    atomicAdd(o + 0, a.x * coeff);
    atomicAdd(o + 1, a.y * coeff);
    atomicAdd(o + 2, a.z * coeff);
    atomicAdd(o + 3, a.w * coeff);
    atomicAdd(o + 4, b.x * coeff);
    atomicAdd(o + 5, b.y * coeff);
    atomicAdd(o + 6, b.z * coeff);
    atomicAdd(o + 7, b.w * coeff);
}

// ---------------- launcher ---------------------------------------------------
extern "C" void kernel_launch(void* const* d_in, const int* in_sizes, int n_in,
                              void* d_out, int out_size) {
    const float* x      = (const float*)d_in[0];
    const int*   ei     = (const int*)  d_in[1];   // int32: JAX x64-disabled downcast
    const float* W1     = (const float*)d_in[2];
    const float* a_src1 = (const float*)d_in[3];
    const float* a_dst1 = (const float*)d_in[4];
    const float* b1     = (const float*)d_in[5];
    const float* W2     = (const float*)d_in[6];
    const float* a_src2 = (const float*)d_in[7];
    const float* a_dst2 = (const float*)d_in[8];
    const float* b2     = (const float*)d_in[9];
    float*       out    = (float*)      d_out;

    const int N  = in_sizes[0] / IN_CH;    // 50000
    const int E  = in_sizes[1] / 2;        // 800000
    const int ET = E + N;                  // + self loops

    // K0: init
    {
        int total = N * F1;
        k_init<<<(total + 255) / 256, 256>>>(b1, b2, out, N);
    }
    // K1: gemm1 + alphas
    k_gemm1<<<(N + 15) / 16, 128>>>(x, W1, a_src1, a_dst1, N);
    // K2: edge pass A layer 1
    k_edgeA1<<<(ET + 255) / 256, 256>>>(ei, E, ET);
    // K3: edge pass B layer 1 (warp per edge)
    {
        long long threads = (long long)ET * 32;
        k_edgeB1<<<(unsigned)((threads + 255) / 256), 256>>>(ei, E, ET);
    }
    // K4: elu + gemm2 + alphas
    k_gemm2<<<(N + 7) / 8, 256>>>(W2, a_src2, a_dst2, N);
    // K5: edge pass A layer 2
    k_edgeA2<<<(ET + 255) / 256, 256>>>(ei, E, ET);
    // K6: edge pass B layer 2
    k_edgeB2<<<(ET + 255) / 256, 256>>>(ei, out, E, ET);
}

// round 3
// speedup vs baseline: 1.4516x; 1.4516x over previous
#include <cuda_runtime.h>
#include <cuda_bf16.h>

#define N_NODES 50000
#define IN_CH   128
#define F1      128     // HEADS*HID
#define HEADS   4
#define HID     32
#define OUT_CH  8
#define NEG_SLOPE 0.2f
#define MAX_ET  (800000 + N_NODES)

// ---------------- scratch (device globals) ----------------------------------
__device__ float g_h1 [N_NODES * F1];      // layer-1 linear output
__device__ float g_as1[N_NODES * HEADS];
__device__ float g_ad1[N_NODES * HEADS];
__device__ float g_out1[N_NODES * F1];     // aggregated layer-1 output (+bias)
__device__ float g_h2 [N_NODES * OUT_CH];
__device__ float g_as2[N_NODES];
__device__ float g_ad2[N_NODES];
// CSR by destination
__device__ int g_deg[N_NODES];
__device__ int g_off[N_NODES + 1];
__device__ int g_cur[N_NODES];
__device__ int g_srclist[MAX_ET];

__device__ __forceinline__ float lrelu(float x) { return x > 0.f ? x : NEG_SLOPE * x; }

// ---------------- C0: seed degree with 1 (self-loop) -------------------------
__global__ void k_deg_init(int N) {
    int i = blockIdx.x * blockDim.x + threadIdx.x;
    if (i < N) g_deg[i] = 1;
}

// ---------------- C1: histogram over real edges ------------------------------
__global__ void k_hist(const int* __restrict__ ei, int E) {
    int e = blockIdx.x * blockDim.x + threadIdx.x;
    if (e < E) atomicAdd(&g_deg[ei[E + e]], 1);
}

// ---------------- C2: single-block exclusive scan + self-loop placement ------
__global__ void k_scan(int N) {
    __shared__ int part[1024];
    const int t = threadIdx.x;
    const int CH = (N + 1023) / 1024;              // 49
    int lo = t * CH, hi = min(lo + CH, N);
    int s = 0;
    for (int i = lo; i < hi; i++) s += g_deg[i];
    part[t] = s;
    __syncthreads();
    for (int off = 1; off < 1024; off <<= 1) {
        int v = (t >= off) ? part[t - off] : 0;
        __syncthreads();
        part[t] += v;
        __syncthreads();
    }
    int run = (t == 0) ? 0 : part[t - 1];
    for (int i = lo; i < hi; i++) {
        g_off[i]     = run;
        g_srclist[run] = i;        // self-loop occupies the first slot
        g_cur[i]     = run + 1;
        run += g_deg[i];
    }
    if (t == 1023) g_off[N] = part[1023];
}

// ---------------- C3: scatter real edges -------------------------------------
__global__ void k_scatter(const int* __restrict__ ei, int E) {
    int e = blockIdx.x * blockDim.x + threadIdx.x;
    if (e >= E) return;
    int s = ei[e], d = ei[E + e];
    int pos = atomicAdd(&g_cur[d], 1);
    g_srclist[pos] = s;
}

// ---------------- K1: h1 = x @ W1 ; alpha_src1/alpha_dst1 --------------------
// 128 threads, 16 rows per block; float4 shared loads
__global__ void k_gemm1(const float* __restrict__ x, const float* __restrict__ W1,
                        const float* __restrict__ a_src1, const float* __restrict__ a_dst1,
                        int N) {
    __shared__ float xs[16][IN_CH];
    __shared__ float hs[16][F1];
    const int t = threadIdx.x;            // output column 0..127
    const int row0 = blockIdx.x * 16;

    #pragma unroll
    for (int r = 0; r < 16; r++) {
        int n = row0 + r;
        xs[r][t] = (n < N) ? x[n * IN_CH + t] : 0.f;
    }
    __syncthreads();

    float acc[16];
    #pragma unroll
    for (int r = 0; r < 16; r++) acc[r] = 0.f;

    for (int k4 = 0; k4 < IN_CH / 4; k4++) {
        float w0 = W1[(k4 * 4 + 0) * F1 + t];
        float w1 = W1[(k4 * 4 + 1) * F1 + t];
        float w2 = W1[(k4 * 4 + 2) * F1 + t];
        float w3 = W1[(k4 * 4 + 3) * F1 + t];
        #pragma unroll
        for (int r = 0; r < 16; r++) {
            float4 xv = reinterpret_cast<const float4*>(xs[r])[k4];
            acc[r] += xv.x * w0 + xv.y * w1 + xv.z * w2 + xv.w * w3;
        }
    }

    #pragma unroll
    for (int r = 0; r < 16; r++) {
        hs[r][t] = acc[r];
        int n = row0 + r;
        if (n < N) g_h1[n * F1 + t] = acc[r];
    }
    __syncthreads();

    // 16 rows * 4 heads * {src,dst} = 128 tasks, one per thread
    const int r    = t >> 3;
    const int q    = t & 7;
    const int head = q & 3;
    const bool is_dst = (q >= 4);
    const float* a = is_dst ? a_dst1 : a_src1;
    float s = 0.f;
    #pragma unroll
    for (int c = 0; c < HID; c++) s += hs[r][head * HID + c] * a[head * HID + c];
    int n = row0 + r;
    if (n < N) {
        if (is_dst) g_ad1[n * HEADS + head] = s;
        else        g_as1[n * HEADS + head] = s;
    }
}

// ---------------- K2: fused layer-1 softmax + aggregation (warp per dst) -----
__global__ void k_agg1(const float* __restrict__ b1, int N) {
    int w    = (blockIdx.x * blockDim.x + threadIdx.x) >> 5;   // dst node
    int lane = threadIdx.x & 31;
    if (w >= N) return;
    const int head = lane >> 3;
    const float ad = g_ad1[w * HEADS + head];
    const int beg = g_off[w], end = g_off[w + 1];

    float4 acc = make_float4(0.f, 0.f, 0.f, 0.f);
    float den = 0.f;
    #pragma unroll 4
    for (int j = beg; j < end; j++) {
        int s = g_srclist[j];
        float e = __expf(lrelu(g_as1[s * HEADS + head] + ad));
        float4 v = reinterpret_cast<const float4*>(g_h1)[s * 32 + lane];
        den   += e;
        acc.x += e * v.x;
        acc.y += e * v.y;
        acc.z += e * v.z;
        acc.w += e * v.w;
    }
    float inv = __frcp_rn(den);
    float4 bias = reinterpret_cast<const float4*>(b1)[lane];
    float4 o;
    o.x = acc.x * inv + bias.x;
    o.y = acc.y * inv + bias.y;
    o.z = acc.z * inv + bias.z;
    o.w = acc.w * inv + bias.w;
    reinterpret_cast<float4*>(g_out1)[w * 32 + lane] = o;
}

// ---------------- K3: elu -> h2 = elu(out1) @ W2 ; alpha2 --------------------
// one warp per node
__global__ void k_gemm2(const float* __restrict__ W2,
                        const float* __restrict__ a_src2, const float* __restrict__ a_dst2,
                        int N) {
    __shared__ float W2s[F1 * OUT_CH];
    __shared__ float a2s[OUT_CH], a2d[OUT_CH];
    int t = threadIdx.x;
    for (int i = t; i < F1 * OUT_CH; i += blockDim.x) W2s[i] = W2[i];
    if (t < OUT_CH) { a2s[t] = a_src2[t]; a2d[t] = a_dst2[t]; }
    __syncthreads();

    int gw   = (blockIdx.x * blockDim.x + t) >> 5;
    int lane = t & 31;
    if (gw >= N) return;
    int n = gw;

    float v[4];
    #pragma unroll
    for (int j = 0; j < 4; j++) {
        float h = g_out1[n * F1 + lane * 4 + j];
        v[j] = h > 0.f ? h : expm1f(h);
    }
    float h2v[OUT_CH];
    #pragma unroll
    for (int o = 0; o < OUT_CH; o++) {
        float p = 0.f;
        #pragma unroll
        for (int j = 0; j < 4; j++) p += v[j] * W2s[(lane * 4 + j) * OUT_CH + o];
        #pragma unroll
        for (int off = 16; off; off >>= 1) p += __shfl_xor_sync(0xFFFFFFFFu, p, off);
        h2v[o] = p;
    }
    if (lane < OUT_CH) g_h2[n * OUT_CH + lane] = h2v[lane];
    if (lane == 0) {
        float s1 = 0.f, s2 = 0.f;
        #pragma unroll
        for (int o = 0; o < OUT_CH; o++) { s1 += h2v[o] * a2s[o]; s2 += h2v[o] * a2d[o]; }
        g_as2[n] = s1;
        g_ad2[n] = s2;
    }
}

// ---------------- K4: fused layer-2 softmax + aggregation --------------------
// 8 lanes per dst node (4 dst per warp), one channel per lane
__global__ void k_agg2(const float* __restrict__ b2, float* __restrict__ out, int N) {
    int gt   = blockIdx.x * blockDim.x + threadIdx.x;
    int d    = gt >> 3;
    int chan = gt & 7;
    if (d >= N) return;
    const float ad = g_ad2[d];
    const int beg = g_off[d], end = g_off[d + 1];
    float acc = 0.f, den = 0.f;
    #pragma unroll 4
    for (int j = beg; j < end; j++) {
        int s = g_srclist[j];
        float e = __expf(lrelu(g_as2[s] + ad));
        den += e;
        acc += e * g_h2[s * OUT_CH + chan];
    }
    out[d * OUT_CH + chan] = acc / den + b2[chan];
}

// ---------------- launcher ---------------------------------------------------
extern "C" void kernel_launch(void* const* d_in, const int* in_sizes, int n_in,
                              void* d_out, int out_size) {
    const float* x      = (const float*)d_in[0];
    const int*   ei     = (const int*)  d_in[1];   // int32 (JAX x64 disabled)
    const float* W1     = (const float*)d_in[2];
    const float* a_src1 = (const float*)d_in[3];
    const float* a_dst1 = (const float*)d_in[4];
    const float* b1     = (const float*)d_in[5];
    const float* W2     = (const float*)d_in[6];
    const float* a_src2 = (const float*)d_in[7];
    const float* a_dst2 = (const float*)d_in[8];
    const float* b2     = (const float*)d_in[9];
    float*       out    = (float*)      d_out;

    const int N = in_sizes[0] / IN_CH;   // 50000
    const int E = in_sizes[1] / 2;       // 800000

    // CSR build
    k_deg_init<<<(N + 255) / 256, 256>>>(N);
    k_hist<<<(E + 255) / 256, 256>>>(ei, E);
    k_scan<<<1, 1024>>>(N);
    k_scatter<<<(E + 255) / 256, 256>>>(ei, E);

    // Layer 1
    k_gemm1<<<(N + 15) / 16, 128>>>(x, W1, a_src1, a_dst1, N);
    k_agg1<<<(N * 32 + 255) / 256, 256>>>(b1, N);

    // Layer 2
    k_gemm2<<<(N + 7) / 8, 256>>>(W2, a_src2, a_dst2, N);
    k_agg2<<<(N * 8 + 255) / 256, 256>>>(b2, out, N);
}

// round 4
// speedup vs baseline: 2.2872x; 1.5756x over previous
#include <cuda_runtime.h>
#include <cuda_bf16.h>

#define N_NODES 50000
#define IN_CH   128
#define F1      128     // HEADS*HID
#define HEADS   4
#define HID     32
#define OUT_CH  8
#define NEG_SLOPE 0.2f
#define MAX_ET  (800000 + N_NODES)
#define SCAN_BLOCKS 49   // ceil(50000/1024)

// ---------------- scratch (device globals) ----------------------------------
__device__ float g_h1 [N_NODES * F1];      // layer-1 linear output
__device__ float g_as1[N_NODES * HEADS];
__device__ float g_ad1[N_NODES * HEADS];
__device__ float g_h2 [N_NODES * OUT_CH];
__device__ float g_as2[N_NODES];
__device__ float g_ad2[N_NODES];
// CSR by destination
__device__ int g_deg[N_NODES];
__device__ int g_off[N_NODES + 1];
__device__ int g_cur[N_NODES];
__device__ int g_srclist[MAX_ET];
__device__ int g_part[64];

__device__ __forceinline__ float lrelu(float x) { return x > 0.f ? x : NEG_SLOPE * x; }

// ---------------- C1: histogram over real edges (4 edges/thread) -------------
__global__ void k_hist(const int* __restrict__ ei, int E) {
    int e4 = (blockIdx.x * blockDim.x + threadIdx.x) * 4;
    if (e4 + 3 < E) {
        int4 d = *reinterpret_cast<const int4*>(&ei[E + e4]);
        atomicAdd(&g_deg[d.x], 1);
        atomicAdd(&g_deg[d.y], 1);
        atomicAdd(&g_deg[d.z], 1);
        atomicAdd(&g_deg[d.w], 1);
    } else {
        for (int e = e4; e < E; e++) atomicAdd(&g_deg[ei[E + e]], 1);
    }
}

// ---------------- C2a: per-block partial sums (deg+1 incl. self loop) --------
__global__ void k_scan_part(int N) {
    __shared__ int red[32];
    int i = blockIdx.x * 1024 + threadIdx.x;
    int v = (i < N) ? g_deg[i] + 1 : 0;
    // warp reduce
    #pragma unroll
    for (int off = 16; off; off >>= 1) v += __shfl_xor_sync(0xFFFFFFFFu, v, off);
    if ((threadIdx.x & 31) == 0) red[threadIdx.x >> 5] = v;
    __syncthreads();
    if (threadIdx.x < 32) {
        int s = red[threadIdx.x];
        #pragma unroll
        for (int off = 16; off; off >>= 1) s += __shfl_xor_sync(0xFFFFFFFFu, s, off);
        if (threadIdx.x == 0) g_part[blockIdx.x] = s;
    }
}

// ---------------- C2b: per-block scan + fill offsets/self-loops --------------
__global__ void k_scan_fill(int N) {
    __shared__ int sdata[1024];
    __shared__ int sbase;
    const int t = threadIdx.x;
    const int b = blockIdx.x;
    const int i = b * 1024 + t;

    if (t == 0) {
        int s = 0;
        #pragma unroll 8
        for (int j = 0; j < b; j++) s += g_part[j];
        sbase = s;
    }
    int val = (i < N) ? g_deg[i] + 1 : 0;
    sdata[t] = val;
    __syncthreads();
    // Hillis-Steele inclusive scan
    #pragma unroll
    for (int off = 1; off < 1024; off <<= 1) {
        int v = (t >= off) ? sdata[t - off] : 0;
        __syncthreads();
        sdata[t] += v;
        __syncthreads();
    }
    int incl = sdata[t];
    int off0 = sbase + incl - val;   // exclusive
    if (i < N) {
        g_off[i]       = off0;
        g_srclist[off0] = i;          // self-loop occupies first slot
        g_cur[i]       = off0 + 1;
        if (i == N - 1) g_off[N] = sbase + incl;
    }
}

// ---------------- C3: scatter real edges (4 edges/thread) --------------------
__global__ void k_scatter(const int* __restrict__ ei, int E) {
    int e4 = (blockIdx.x * blockDim.x + threadIdx.x) * 4;
    if (e4 + 3 < E) {
        int4 s = *reinterpret_cast<const int4*>(&ei[e4]);
        int4 d = *reinterpret_cast<const int4*>(&ei[E + e4]);
        int p0 = atomicAdd(&g_cur[d.x], 1);
        int p1 = atomicAdd(&g_cur[d.y], 1);
        int p2 = atomicAdd(&g_cur[d.z], 1);
        int p3 = atomicAdd(&g_cur[d.w], 1);
        g_srclist[p0] = s.x;
        g_srclist[p1] = s.y;
        g_srclist[p2] = s.z;
        g_srclist[p3] = s.w;
    } else {
        for (int e = e4; e < E; e++) {
            int pos = atomicAdd(&g_cur[ei[E + e]], 1);
            g_srclist[pos] = ei[e];
        }
    }
}

// ---------------- K1: h1 = x @ W1 ; alpha_src1/alpha_dst1 --------------------
__global__ void k_gemm1(const float* __restrict__ x, const float* __restrict__ W1,
                        const float* __restrict__ a_src1, const float* __restrict__ a_dst1,
                        int N) {
    __shared__ float xs[16][IN_CH];
    __shared__ float hs[16][F1];
    const int t = threadIdx.x;            // output column 0..127
    const int row0 = blockIdx.x * 16;

    #pragma unroll
    for (int r = 0; r < 16; r++) {
        int n = row0 + r;
        xs[r][t] = (n < N) ? x[n * IN_CH + t] : 0.f;
    }
    __syncthreads();

    float acc[16];
    #pragma unroll
    for (int r = 0; r < 16; r++) acc[r] = 0.f;

    for (int k4 = 0; k4 < IN_CH / 4; k4++) {
        float w0 = W1[(k4 * 4 + 0) * F1 + t];
        float w1 = W1[(k4 * 4 + 1) * F1 + t];
        float w2 = W1[(k4 * 4 + 2) * F1 + t];
        float w3 = W1[(k4 * 4 + 3) * F1 + t];
        #pragma unroll
        for (int r = 0; r < 16; r++) {
            float4 xv = reinterpret_cast<const float4*>(xs[r])[k4];
            acc[r] += xv.x * w0 + xv.y * w1 + xv.z * w2 + xv.w * w3;
        }
    }

    #pragma unroll
    for (int r = 0; r < 16; r++) {
        hs[r][t] = acc[r];
        int n = row0 + r;
        if (n < N) g_h1[n * F1 + t] = acc[r];
    }
    __syncthreads();

    const int r    = t >> 3;
    const int q    = t & 7;
    const int head = q & 3;
    const bool is_dst = (q >= 4);
    const float* a = is_dst ? a_dst1 : a_src1;
    float s = 0.f;
    #pragma unroll
    for (int c = 0; c < HID; c++) s += hs[r][head * HID + c] * a[head * HID + c];
    int n = row0 + r;
    if (n < N) {
        if (is_dst) g_ad1[n * HEADS + head] = s;
        else        g_as1[n * HEADS + head] = s;
    }
}

// ---------------- K2: fused layer-1 agg + ELU + layer-2 linear ---------------
// warp per dst node; epilogue computes h2 = elu(out1)@W2 and as2/ad2
__global__ void k_agg1(const float* __restrict__ b1, const float* __restrict__ W2,
                       const float* __restrict__ a_src2, const float* __restrict__ a_dst2,
                       int N) {
    __shared__ float W2s[F1 * OUT_CH];
    __shared__ float a2s[OUT_CH], a2d[OUT_CH];
    {
        int t = threadIdx.x;
        for (int i = t; i < F1 * OUT_CH; i += blockDim.x) W2s[i] = W2[i];
        if (t < OUT_CH) { a2s[t] = a_src2[t]; a2d[t] = a_dst2[t]; }
        __syncthreads();
    }

    int w    = (blockIdx.x * blockDim.x + threadIdx.x) >> 5;   // dst node
    int lane = threadIdx.x & 31;
    if (w >= N) return;
    const int head = lane >> 3;
    const float ad = g_ad1[w * HEADS + head];
    const int beg = g_off[w], end = g_off[w + 1];

    float4 acc = make_float4(0.f, 0.f, 0.f, 0.f);
    float den = 0.f;
    #pragma unroll 4
    for (int j = beg; j < end; j++) {
        int s = g_srclist[j];
        float e = __expf(lrelu(g_as1[s * HEADS + head] + ad));
        float4 v = reinterpret_cast<const float4*>(g_h1)[s * 32 + lane];
        den   += e;
        acc.x += e * v.x;
        acc.y += e * v.y;
        acc.z += e * v.z;
        acc.w += e * v.w;
    }
    float inv = __frcp_rn(den);
    float4 bias = reinterpret_cast<const float4*>(b1)[lane];
    float v0 = acc.x * inv + bias.x;
    float v1 = acc.y * inv + bias.y;
    float v2 = acc.z * inv + bias.z;
    float v3 = acc.w * inv + bias.w;
    // ELU
    v0 = v0 > 0.f ? v0 : expm1f(v0);
    v1 = v1 > 0.f ? v1 : expm1f(v1);
    v2 = v2 > 0.f ? v2 : expm1f(v2);
    v3 = v3 > 0.f ? v3 : expm1f(v3);

    // h2 = elu(out1) @ W2  (warp-wide reduction per output channel)
    float h2v[OUT_CH];
    const float* Wrow = &W2s[lane * 4 * OUT_CH];
    #pragma unroll
    for (int o = 0; o < OUT_CH; o++) {
        float p = v0 * Wrow[0 * OUT_CH + o] + v1 * Wrow[1 * OUT_CH + o]
                + v2 * Wrow[2 * OUT_CH + o] + v3 * Wrow[3 * OUT_CH + o];
        #pragma unroll
        for (int off = 16; off; off >>= 1) p += __shfl_xor_sync(0xFFFFFFFFu, p, off);
        h2v[o] = p;
    }
    if (lane < OUT_CH) g_h2[w * OUT_CH + lane] = h2v[lane];
    if (lane == 0) {
        float s1 = 0.f, s2 = 0.f;
        #pragma unroll
        for (int o = 0; o < OUT_CH; o++) { s1 += h2v[o] * a2s[o]; s2 += h2v[o] * a2d[o]; }
        g_as2[w] = s1;
        g_ad2[w] = s2;
    }
}

// ---------------- K3: fused layer-2 softmax + aggregation --------------------
// 8 lanes per dst node, one channel per lane
__global__ void k_agg2(const float* __restrict__ b2, float* __restrict__ out, int N) {
    int gt   = blockIdx.x * blockDim.x + threadIdx.x;
    int d    = gt >> 3;
    int chan = gt & 7;
    if (d >= N) return;
    const float ad = g_ad2[d];
    const int beg = g_off[d], end = g_off[d + 1];
    float acc = 0.f, den = 0.f;
    #pragma unroll 4
    for (int j = beg; j < end; j++) {
        int s = g_srclist[j];
        float e = __expf(lrelu(g_as2[s] + ad));
        den += e;
        acc += e * g_h2[s * OUT_CH + chan];
    }
    out[d * OUT_CH + chan] = acc / den + b2[chan];
}

// ---------------- launcher ---------------------------------------------------
extern "C" void kernel_launch(void* const* d_in, const int* in_sizes, int n_in,
                              void* d_out, int out_size) {
    const float* x      = (const float*)d_in[0];
    const int*   ei     = (const int*)  d_in[1];   // int32 (JAX x64 disabled)
    const float* W1     = (const float*)d_in[2];
    const float* a_src1 = (const float*)d_in[3];
    const float* a_dst1 = (const float*)d_in[4];
    const float* b1     = (const float*)d_in[5];
    const float* W2     = (const float*)d_in[6];
    const float* a_src2 = (const float*)d_in[7];
    const float* a_dst2 = (const float*)d_in[8];
    const float* b2     = (const float*)d_in[9];
    float*       out    = (float*)      d_out;

    const int N = in_sizes[0] / IN_CH;   // 50000
    const int E = in_sizes[1] / 2;       // 800000

    // zero degree histogram
    void* deg_ptr = nullptr;
    cudaGetSymbolAddress(&deg_ptr, g_deg);
    cudaMemsetAsync(deg_ptr, 0, N * sizeof(int));

    // CSR build
    {
        int nt = (E + 3) / 4;
        k_hist<<<(nt + 255) / 256, 256>>>(ei, E);
    }
    k_scan_part<<<SCAN_BLOCKS, 1024>>>(N);
    k_scan_fill<<<SCAN_BLOCKS, 1024>>>(N);
    {
        int nt = (E + 3) / 4;
        k_scatter<<<(nt + 255) / 256, 256>>>(ei, E);
    }

    // Layer 1 linear
    k_gemm1<<<(N + 15) / 16, 128>>>(x, W1, a_src1, a_dst1, N);
    // Fused layer-1 aggregation + ELU + layer-2 linear
    k_agg1<<<(N * 32 + 255) / 256, 256>>>(b1, W2, a_src2, a_dst2, N);
    // Layer-2 aggregation
    k_agg2<<<(N * 8 + 255) / 256, 256>>>(b2, out, N);
}

// round 5
// speedup vs baseline: 2.4350x; 1.0646x over previous
#include <cuda_runtime.h>
#include <cuda_fp16.h>

#define N_NODES 50000
#define IN_CH   128
#define F1      128     // HEADS*HID
#define HEADS   4
#define HID     32
#define OUT_CH  8
#define NEG_SLOPE 0.2f
#define MAX_ET  (800000 + N_NODES)
#define SCAN_BLOCKS 49   // ceil(50000/1024)

// ---------------- scratch (device globals) ----------------------------------
__device__ __half g_h1h[N_NODES * F1];     // layer-1 linear output (fp16)
__device__ float g_as1[N_NODES * HEADS];
__device__ float g_ad1[N_NODES * HEADS];
__device__ float g_h2 [N_NODES * OUT_CH];
__device__ float g_as2[N_NODES];
__device__ float g_ad2[N_NODES];
// CSR by destination
__device__ int g_deg[N_NODES];
__device__ int g_off[N_NODES + 1];
__device__ int g_cur[N_NODES];
__device__ int g_srclist[MAX_ET];
__device__ int g_part[64];

__device__ __forceinline__ float lrelu(float x) { return x > 0.f ? x : NEG_SLOPE * x; }

// ---------------- C1: histogram over real edges (4 edges/thread) -------------
__global__ void k_hist(const int* __restrict__ ei, int E) {
    int e4 = (blockIdx.x * blockDim.x + threadIdx.x) * 4;
    if (e4 + 3 < E) {
        int4 d = *reinterpret_cast<const int4*>(&ei[E + e4]);
        atomicAdd(&g_deg[d.x], 1);
        atomicAdd(&g_deg[d.y], 1);
        atomicAdd(&g_deg[d.z], 1);
        atomicAdd(&g_deg[d.w], 1);
    } else {
        for (int e = e4; e < E; e++) atomicAdd(&g_deg[ei[E + e]], 1);
    }
}

// ---------------- C2a: per-block partial sums (deg+1 incl. self loop) --------
__global__ void k_scan_part(int N) {
    __shared__ int red[32];
    int i = blockIdx.x * 1024 + threadIdx.x;
    int v = (i < N) ? g_deg[i] + 1 : 0;
    #pragma unroll
    for (int off = 16; off; off >>= 1) v += __shfl_xor_sync(0xFFFFFFFFu, v, off);
    if ((threadIdx.x & 31) == 0) red[threadIdx.x >> 5] = v;
    __syncthreads();
    if (threadIdx.x < 32) {
        int s = red[threadIdx.x];
        #pragma unroll
        for (int off = 16; off; off >>= 1) s += __shfl_xor_sync(0xFFFFFFFFu, s, off);
        if (threadIdx.x == 0) g_part[blockIdx.x] = s;
    }
}

// ---------------- C2b: per-block scan + fill offsets/self-loops --------------
__global__ void k_scan_fill(int N) {
    __shared__ int sdata[1024];
    __shared__ int sbase;
    const int t = threadIdx.x;
    const int b = blockIdx.x;
    const int i = b * 1024 + t;

    if (t == 0) {
        int s = 0;
        #pragma unroll 8
        for (int j = 0; j < b; j++) s += g_part[j];
        sbase = s;
    }
    int val = (i < N) ? g_deg[i] + 1 : 0;
    sdata[t] = val;
    __syncthreads();
    #pragma unroll
    for (int off = 1; off < 1024; off <<= 1) {
        int v = (t >= off) ? sdata[t - off] : 0;
        __syncthreads();
        sdata[t] += v;
        __syncthreads();
    }
    int incl = sdata[t];
    int off0 = sbase + incl - val;   // exclusive
    if (i < N) {
        g_off[i]        = off0;
        g_srclist[off0] = i;          // self-loop occupies first slot
        g_cur[i]        = off0 + 1;
        if (i == N - 1) g_off[N] = sbase + incl;
    }
}

// ---------------- C3: scatter real edges (8 edges/thread) --------------------
__global__ void k_scatter(const int* __restrict__ ei, int E) {
    int e8 = (blockIdx.x * blockDim.x + threadIdx.x) * 8;
    if (e8 + 7 < E) {
        int4 s0 = *reinterpret_cast<const int4*>(&ei[e8]);
        int4 s1 = *reinterpret_cast<const int4*>(&ei[e8 + 4]);
        int4 d0 = *reinterpret_cast<const int4*>(&ei[E + e8]);
        int4 d1 = *reinterpret_cast<const int4*>(&ei[E + e8 + 4]);
        int p0 = atomicAdd(&g_cur[d0.x], 1);
        int p1 = atomicAdd(&g_cur[d0.y], 1);
        int p2 = atomicAdd(&g_cur[d0.z], 1);
        int p3 = atomicAdd(&g_cur[d0.w], 1);
        int p4 = atomicAdd(&g_cur[d1.x], 1);
        int p5 = atomicAdd(&g_cur[d1.y], 1);
        int p6 = atomicAdd(&g_cur[d1.z], 1);
        int p7 = atomicAdd(&g_cur[d1.w], 1);
        g_srclist[p0] = s0.x;
        g_srclist[p1] = s0.y;
        g_srclist[p2] = s0.z;
        g_srclist[p3] = s0.w;
        g_srclist[p4] = s1.x;
        g_srclist[p5] = s1.y;
        g_srclist[p6] = s1.z;
        g_srclist[p7] = s1.w;
    } else {
        for (int e = e8; e < E; e++) {
            int pos = atomicAdd(&g_cur[ei[E + e]], 1);
            g_srclist[pos] = ei[e];
        }
    }
}

// ---------------- K1: h1 = x @ W1 ; alpha_src1/alpha_dst1 --------------------
__global__ void k_gemm1(const float* __restrict__ x, const float* __restrict__ W1,
                        const float* __restrict__ a_src1, const float* __restrict__ a_dst1,
                        int N) {
    __shared__ float xs[16][IN_CH];
    __shared__ float hs[16][F1];
    const int t = threadIdx.x;            // output column 0..127
    const int row0 = blockIdx.x * 16;

    #pragma unroll
    for (int r = 0; r < 16; r++) {
        int n = row0 + r;
        xs[r][t] = (n < N) ? x[n * IN_CH + t] : 0.f;
    }
    __syncthreads();

    float acc[16];
    #pragma unroll
    for (int r = 0; r < 16; r++) acc[r] = 0.f;

    for (int k4 = 0; k4 < IN_CH / 4; k4++) {
        float w0 = W1[(k4 * 4 + 0) * F1 + t];
        float w1 = W1[(k4 * 4 + 1) * F1 + t];
        float w2 = W1[(k4 * 4 + 2) * F1 + t];
        float w3 = W1[(k4 * 4 + 3) * F1 + t];
        #pragma unroll
        for (int r = 0; r < 16; r++) {
            float4 xv = reinterpret_cast<const float4*>(xs[r])[k4];
            acc[r] += xv.x * w0 + xv.y * w1 + xv.z * w2 + xv.w * w3;
        }
    }

    #pragma unroll
    for (int r = 0; r < 16; r++) {
        hs[r][t] = acc[r];
        int n = row0 + r;
        if (n < N) g_h1h[n * F1 + t] = __float2half(acc[r]);
    }
    __syncthreads();

    const int r    = t >> 3;
    const int q    = t & 7;
    const int head = q & 3;
    const bool is_dst = (q >= 4);
    const float* a = is_dst ? a_dst1 : a_src1;
    float s = 0.f;
    #pragma unroll
    for (int c = 0; c < HID; c++) s += hs[r][head * HID + c] * a[head * HID + c];
    int n = row0 + r;
    if (n < N) {
        if (is_dst) g_ad1[n * HEADS + head] = s;
        else        g_as1[n * HEADS + head] = s;
    }
}

// ---------------- K2: fused layer-1 agg + ELU + layer-2 linear ---------------
// warp per dst node; epilogue computes h2 = elu(out1)@W2 and as2/ad2
__global__ void k_agg1(const float* __restrict__ b1, const float* __restrict__ W2,
                       const float* __restrict__ a_src2, const float* __restrict__ a_dst2,
                       int N) {
    __shared__ float W2s[F1 * OUT_CH];
    __shared__ float a2s[OUT_CH], a2d[OUT_CH];
    {
        int t = threadIdx.x;
        for (int i = t; i < F1 * OUT_CH; i += blockDim.x) W2s[i] = W2[i];
        if (t < OUT_CH) { a2s[t] = a_src2[t]; a2d[t] = a_dst2[t]; }
        __syncthreads();
    }

    int w    = (blockIdx.x * blockDim.x + threadIdx.x) >> 5;   // dst node
    int lane = threadIdx.x & 31;
    if (w >= N) return;
    const int head = lane >> 3;
    const float ad = g_ad1[w * HEADS + head];
    const int beg = g_off[w], end = g_off[w + 1];

    const uint2* h1v = reinterpret_cast<const uint2*>(g_h1h);

    float4 acc = make_float4(0.f, 0.f, 0.f, 0.f);
    float den = 0.f;
    #pragma unroll 4
    for (int j = beg; j < end; j++) {
        int s = g_srclist[j];
        float e = __expf(lrelu(g_as1[s * HEADS + head] + ad));
        uint2 u = h1v[s * 32 + lane];                 // 4 halves
        float2 f0 = __half22float2(*reinterpret_cast<const __half2*>(&u.x));
        float2 f1 = __half22float2(*reinterpret_cast<const __half2*>(&u.y));
        den   += e;
        acc.x += e * f0.x;
        acc.y += e * f0.y;
        acc.z += e * f1.x;
        acc.w += e * f1.y;
    }
    float inv = __frcp_rn(den);
    float4 bias = reinterpret_cast<const float4*>(b1)[lane];
    float v0 = acc.x * inv + bias.x;
    float v1 = acc.y * inv + bias.y;
    float v2 = acc.z * inv + bias.z;
    float v3 = acc.w * inv + bias.w;
    // ELU
    v0 = v0 > 0.f ? v0 : expm1f(v0);
    v1 = v1 > 0.f ? v1 : expm1f(v1);
    v2 = v2 > 0.f ? v2 : expm1f(v2);
    v3 = v3 > 0.f ? v3 : expm1f(v3);

    // h2 = elu(out1) @ W2  (warp-wide reduction per output channel)
    float h2v[OUT_CH];
    const float* Wrow = &W2s[lane * 4 * OUT_CH];
    #pragma unroll
    for (int o = 0; o < OUT_CH; o++) {
        float p = v0 * Wrow[0 * OUT_CH + o] + v1 * Wrow[1 * OUT_CH + o]
                + v2 * Wrow[2 * OUT_CH + o] + v3 * Wrow[3 * OUT_CH + o];
        #pragma unroll
        for (int off = 16; off; off >>= 1) p += __shfl_xor_sync(0xFFFFFFFFu, p, off);
        h2v[o] = p;
    }
    if (lane < OUT_CH) g_h2[w * OUT_CH + lane] = h2v[lane];
    if (lane == 0) {
        float s1 = 0.f, s2 = 0.f;
        #pragma unroll
        for (int o = 0; o < OUT_CH; o++) { s1 += h2v[o] * a2s[o]; s2 += h2v[o] * a2d[o]; }
        g_as2[w] = s1;
        g_ad2[w] = s2;
    }
}

// ---------------- K3: fused layer-2 softmax + aggregation --------------------
// 8 lanes per dst node, one channel per lane
__global__ void k_agg2(const float* __restrict__ b2, float* __restrict__ out, int N) {
    int gt   = blockIdx.x * blockDim.x + threadIdx.x;
    int d    = gt >> 3;
    int chan = gt & 7;
    if (d >= N) return;
    const float ad = g_ad2[d];
    const int beg = g_off[d], end = g_off[d + 1];
    float acc = 0.f, den = 0.f;
    #pragma unroll 4
    for (int j = beg; j < end; j++) {
        int s = g_srclist[j];
        float e = __expf(lrelu(g_as2[s] + ad));
        den += e;
        acc += e * g_h2[s * OUT_CH + chan];
    }
    out[d * OUT_CH + chan] = acc / den + b2[chan];
}

// ---------------- launcher ---------------------------------------------------
extern "C" void kernel_launch(void* const* d_in, const int* in_sizes, int n_in,
                              void* d_out, int out_size) {
    const float* x      = (const float*)d_in[0];
    const int*   ei     = (const int*)  d_in[1];   // int32 (JAX x64 disabled)
    const float* W1     = (const float*)d_in[2];
    const float* a_src1 = (const float*)d_in[3];
    const float* a_dst1 = (const float*)d_in[4];
    const float* b1     = (const float*)d_in[5];
    const float* W2     = (const float*)d_in[6];
    const float* a_src2 = (const float*)d_in[7];
    const float* a_dst2 = (const float*)d_in[8];
    const float* b2     = (const float*)d_in[9];
    float*       out    = (float*)      d_out;

    const int N = in_sizes[0] / IN_CH;   // 50000
    const int E = in_sizes[1] / 2;       // 800000

    // side stream + events, created once on the (uncaptured) correctness call
    static cudaStream_t s2 = []() {
        cudaStream_t s; cudaStreamCreateWithFlags(&s, cudaStreamNonBlocking); return s;
    }();
    static cudaEvent_t ev0 = []() {
        cudaEvent_t e; cudaEventCreateWithFlags(&e, cudaEventDisableTiming); return e;
    }();
    static cudaEvent_t ev1 = []() {
        cudaEvent_t e; cudaEventCreateWithFlags(&e, cudaEventDisableTiming); return e;
    }();

    // fork: CSR build on s2, gemm1 on main stream
    cudaEventRecord(ev0, 0);
    cudaStreamWaitEvent(s2, ev0, 0);

    // --- branch A (s2): CSR build ---
    void* deg_ptr = nullptr;
    cudaGetSymbolAddress(&deg_ptr, g_deg);
    cudaMemsetAsync(deg_ptr, 0, N * sizeof(int), s2);
    {
        int nt = (E + 3) / 4;
        k_hist<<<(nt + 255) / 256, 256, 0, s2>>>(ei, E);
    }
    k_scan_part<<<SCAN_BLOCKS, 1024, 0, s2>>>(N);
    k_scan_fill<<<SCAN_BLOCKS, 1024, 0, s2>>>(N);
    {
        int nt = (E + 7) / 8;
        k_scatter<<<(nt + 255) / 256, 256, 0, s2>>>(ei, E);
    }
    cudaEventRecord(ev1, s2);

    // --- branch B (main): layer-1 linear ---
    k_gemm1<<<(N + 15) / 16, 128>>>(x, W1, a_src1, a_dst1, N);

    // join
    cudaStreamWaitEvent(0, ev1, 0);

    // fused layer-1 aggregation + ELU + layer-2 linear
    k_agg1<<<(N * 32 + 255) / 256, 256>>>(b1, W2, a_src2, a_dst2, N);
    // layer-2 aggregation
    k_agg2<<<(N * 8 + 255) / 256, 256>>>(b2, out, N);
}

// round 6
// speedup vs baseline: 3.1379x; 1.2887x over previous
#include <cuda_runtime.h>
#include <cuda_fp16.h>

#define N_NODES 50000
#define IN_CH   128
#define F1      128     // HEADS*HID
#define HEADS   4
#define HID     32
#define OUT_CH  8
#define NEG_SLOPE 0.2f
#define MAX_ET  (800000 + N_NODES)
#define SCAN_BLOCKS 49   // ceil(50000/1024)

// ---------------- scratch (device globals) ----------------------------------
__device__ __half g_h1h[N_NODES * F1];     // layer-1 linear output (fp16)
__device__ float g_as1[N_NODES * HEADS];
__device__ float g_ad1[N_NODES * HEADS];
__device__ float g_h2 [N_NODES * OUT_CH];
__device__ float g_as2[N_NODES];
__device__ float g_ad2[N_NODES];
// CSR by destination
__device__ int g_deg[N_NODES];
__device__ int g_off[N_NODES + 1];
__device__ int g_cur[N_NODES];
__device__ int g_srclist[MAX_ET];
__device__ int g_part[64];

__device__ __forceinline__ float lrelu(float x) { return x > 0.f ? x : NEG_SLOPE * x; }

// ---------------- C1: histogram over real edges (4 edges/thread) -------------
__global__ void k_hist(const int* __restrict__ ei, int E) {
    int e4 = (blockIdx.x * blockDim.x + threadIdx.x) * 4;
    if (e4 + 3 < E) {
        int4 d = *reinterpret_cast<const int4*>(&ei[E + e4]);
        atomicAdd(&g_deg[d.x], 1);
        atomicAdd(&g_deg[d.y], 1);
        atomicAdd(&g_deg[d.z], 1);
        atomicAdd(&g_deg[d.w], 1);
    } else {
        for (int e = e4; e < E; e++) atomicAdd(&g_deg[ei[E + e]], 1);
    }
}

// ---------------- C2a: per-block partial sums (deg+1 incl. self loop) --------
__global__ void k_scan_part(int N) {
    __shared__ int red[32];
    int i = blockIdx.x * 1024 + threadIdx.x;
    int v = (i < N) ? g_deg[i] + 1 : 0;
    #pragma unroll
    for (int off = 16; off; off >>= 1) v += __shfl_xor_sync(0xFFFFFFFFu, v, off);
    if ((threadIdx.x & 31) == 0) red[threadIdx.x >> 5] = v;
    __syncthreads();
    if (threadIdx.x < 32) {
        int s = red[threadIdx.x];
        #pragma unroll
        for (int off = 16; off; off >>= 1) s += __shfl_xor_sync(0xFFFFFFFFu, s, off);
        if (threadIdx.x == 0) g_part[blockIdx.x] = s;
    }
}

// ---------------- C2b: per-block scan + fill offsets/self-loops --------------
__global__ void k_scan_fill(int N) {
    __shared__ int sdata[1024];
    __shared__ int sbase;
    const int t = threadIdx.x;
    const int b = blockIdx.x;
    const int i = b * 1024 + t;

    if (t == 0) {
        int s = 0;
        #pragma unroll 8
        for (int j = 0; j < b; j++) s += g_part[j];
        sbase = s;
    }
    int val = (i < N) ? g_deg[i] + 1 : 0;
    sdata[t] = val;
    __syncthreads();
    #pragma unroll
    for (int off = 1; off < 1024; off <<= 1) {
        int v = (t >= off) ? sdata[t - off] : 0;
        __syncthreads();
        sdata[t] += v;
        __syncthreads();
    }
    int incl = sdata[t];
    int off0 = sbase + incl - val;   // exclusive
    if (i < N) {
        g_off[i]        = off0;
        g_srclist[off0] = i;          // self-loop occupies first slot
        g_cur[i]        = off0 + 1;
        if (i == N - 1) g_off[N] = sbase + incl;
    }
}

// ---------------- C3: scatter real edges (8 edges/thread) --------------------
__global__ void k_scatter(const int* __restrict__ ei, int E) {
    int e8 = (blockIdx.x * blockDim.x + threadIdx.x) * 8;
    if (e8 + 7 < E) {
        int4 s0 = *reinterpret_cast<const int4*>(&ei[e8]);
        int4 s1 = *reinterpret_cast<const int4*>(&ei[e8 + 4]);
        int4 d0 = *reinterpret_cast<const int4*>(&ei[E + e8]);
        int4 d1 = *reinterpret_cast<const int4*>(&ei[E + e8 + 4]);
        int p0 = atomicAdd(&g_cur[d0.x], 1);
        int p1 = atomicAdd(&g_cur[d0.y], 1);
        int p2 = atomicAdd(&g_cur[d0.z], 1);
        int p3 = atomicAdd(&g_cur[d0.w], 1);
        int p4 = atomicAdd(&g_cur[d1.x], 1);
        int p5 = atomicAdd(&g_cur[d1.y], 1);
        int p6 = atomicAdd(&g_cur[d1.z], 1);
        int p7 = atomicAdd(&g_cur[d1.w], 1);
        g_srclist[p0] = s0.x;
        g_srclist[p1] = s0.y;
        g_srclist[p2] = s0.z;
        g_srclist[p3] = s0.w;
        g_srclist[p4] = s1.x;
        g_srclist[p5] = s1.y;
        g_srclist[p6] = s1.z;
        g_srclist[p7] = s1.w;
    } else {
        for (int e = e8; e < E; e++) {
            int pos = atomicAdd(&g_cur[ei[E + e]], 1);
            g_srclist[pos] = ei[e];
        }
    }
}

// ---------------- K1: h1 = x @ W1 ; alpha_src1/alpha_dst1 --------------------
// 128 threads, 16 rows/block; packed f32x2 FMA; conflict-free epilogue
__global__ void k_gemm1(const float* __restrict__ x, const float* __restrict__ W1,
                        const float* __restrict__ a_src1, const float* __restrict__ a_dst1,
                        int N) {
    __shared__ float xs2[IN_CH][20];   // [k][r]; 20-float rows: 16B aligned, 4-way write conflicts only
    __shared__ float hs[16][F1];
    const int t = threadIdx.x;            // output column 0..127
    const int row0 = blockIdx.x * 16;

    #pragma unroll
    for (int r = 0; r < 16; r++) {
        int n = row0 + r;
        xs2[t][r] = (n < N) ? x[n * IN_CH + t] : 0.f;
    }
    __syncthreads();

    unsigned long long accp[8];            // accp[p] = rows (2p, 2p+1)
    #pragma unroll
    for (int i = 0; i < 8; i++) accp[i] = 0ull;

    #pragma unroll 4
    for (int k = 0; k < IN_CH; k++) {
        float w = W1[k * F1 + t];
        unsigned long long w2;
        asm("mov.b64 %0, {%1, %1};" : "=l"(w2) : "f"(w));
        const ulonglong2* xr = reinterpret_cast<const ulonglong2*>(&xs2[k][0]);
        #pragma unroll
        for (int i = 0; i < 4; i++) {
            ulonglong2 u = xr[i];          // rows 4i..4i+3 (broadcast load)
            asm("fma.rn.f32x2 %0, %1, %2, %0;" : "+l"(accp[2*i  ]) : "l"(u.x), "l"(w2));
            asm("fma.rn.f32x2 %0, %1, %2, %0;" : "+l"(accp[2*i+1]) : "l"(u.y), "l"(w2));
        }
    }

    #pragma unroll
    for (int i = 0; i < 8; i++) {
        float lo, hi;
        asm("mov.b64 {%0, %1}, %2;" : "=f"(lo), "=f"(hi) : "l"(accp[i]));
        int r0 = 2 * i, r1 = 2 * i + 1;
        hs[r0][t] = lo;
        hs[r1][t] = hi;
        int n0 = row0 + r0, n1 = row0 + r1;
        if (n0 < N) g_h1h[n0 * F1 + t] = __float2half(lo);
        if (n1 < N) g_h1h[n1 * F1 + t] = __float2half(hi);
    }
    __syncthreads();

    // 16 rows * 4 heads * {src,dst} = 128 tasks, one per thread.
    // Rotate the channel index by t so all lanes hit distinct banks.
    const int r    = t >> 3;
    const int q    = t & 7;
    const int head = q & 3;
    const bool is_dst = (q >= 4);
    const float* a = is_dst ? a_dst1 : a_src1;
    float s = 0.f;
    #pragma unroll
    for (int c0 = 0; c0 < HID; c0++) {
        int c = (c0 + t) & (HID - 1);
        s += hs[r][head * HID + c] * a[head * HID + c];
    }
    int n = row0 + r;
    if (n < N) {
        if (is_dst) g_ad1[n * HEADS + head] = s;
        else        g_as1[n * HEADS + head] = s;
    }
}

// ---------------- K2: fused layer-1 agg + ELU + layer-2 linear ---------------
// warp per dst node; W2 transposed in smem for conflict-free epilogue
__global__ void k_agg1(const float* __restrict__ b1, const float* __restrict__ W2,
                       const float* __restrict__ a_src2, const float* __restrict__ a_dst2,
                       int N) {
    __shared__ float W2t[OUT_CH][F1];      // transposed: W2t[o][c] = W2[c*8+o]
    __shared__ float a2s[OUT_CH], a2d[OUT_CH];
    {
        int tt = threadIdx.x;
        for (int i = tt; i < F1 * OUT_CH; i += blockDim.x) {
            int c = i >> 3, o = i & 7;
            W2t[o][c] = W2[i];
        }
        if (tt < OUT_CH) { a2s[tt] = a_src2[tt]; a2d[tt] = a_dst2[tt]; }
        __syncthreads();
    }

    int w    = (blockIdx.x * blockDim.x + threadIdx.x) >> 5;   // dst node
    int lane = threadIdx.x & 31;
    if (w >= N) return;
    const int head = lane >> 3;
    const float ad = g_ad1[w * HEADS + head];
    const int beg = g_off[w], end = g_off[w + 1];

    const uint2* h1v = reinterpret_cast<const uint2*>(g_h1h);

    float4 acc = make_float4(0.f, 0.f, 0.f, 0.f);
    float den = 0.f;
    #pragma unroll 4
    for (int j = beg; j < end; j++) {
        int s = g_srclist[j];
        float e = __expf(lrelu(g_as1[s * HEADS + head] + ad));
        uint2 u = h1v[s * 32 + lane];                 // 4 halves
        float2 f0 = __half22float2(*reinterpret_cast<const __half2*>(&u.x));
        float2 f1 = __half22float2(*reinterpret_cast<const __half2*>(&u.y));
        den   += e;
        acc.x += e * f0.x;
        acc.y += e * f0.y;
        acc.z += e * f1.x;
        acc.w += e * f1.y;
    }
    float inv = __frcp_rn(den);
    float4 bias = reinterpret_cast<const float4*>(b1)[lane];
    float v0 = acc.x * inv + bias.x;
    float v1 = acc.y * inv + bias.y;
    float v2 = acc.z * inv + bias.z;
    float v3 = acc.w * inv + bias.w;
    // ELU
    v0 = v0 > 0.f ? v0 : expm1f(v0);
    v1 = v1 > 0.f ? v1 : expm1f(v1);
    v2 = v2 > 0.f ? v2 : expm1f(v2);
    v3 = v3 > 0.f ? v3 : expm1f(v3);

    // h2 = elu(out1) @ W2  — conflict-free: lanes read W2t[o][lane*4..+3]
    float h2v[OUT_CH];
    #pragma unroll
    for (int o = 0; o < OUT_CH; o++) {
        float4 wv = *reinterpret_cast<const float4*>(&W2t[o][lane * 4]);
        float p = v0 * wv.x + v1 * wv.y + v2 * wv.z + v3 * wv.w;
        #pragma unroll
        for (int off = 16; off; off >>= 1) p += __shfl_xor_sync(0xFFFFFFFFu, p, off);
        h2v[o] = p;
    }
    if (lane < OUT_CH) g_h2[w * OUT_CH + lane] = h2v[lane];
    if (lane == 0) {
        float s1 = 0.f, s2 = 0.f;
        #pragma unroll
        for (int o = 0; o < OUT_CH; o++) { s1 += h2v[o] * a2s[o]; s2 += h2v[o] * a2d[o]; }
        g_as2[w] = s1;
        g_ad2[w] = s2;
    }
}

// ---------------- K3: fused layer-2 softmax + aggregation --------------------
// warp per dst node: 4 edge-slots x 8 channels
__global__ void k_agg2(const float* __restrict__ b2, float* __restrict__ out, int N) {
    int w    = (blockIdx.x * blockDim.x + threadIdx.x) >> 5;   // dst node
    int lane = threadIdx.x & 31;
    if (w >= N) return;
    const int eg   = lane >> 3;   // edge slot 0..3
    const int chan = lane & 7;
    const float ad = g_ad2[w];
    const int beg = g_off[w], end = g_off[w + 1];
    float acc = 0.f, den = 0.f;
    for (int j = beg + eg; j < end; j += 4) {
        int s = g_srclist[j];
        float e = __expf(lrelu(g_as2[s] + ad));
        den += e;
        acc += e * g_h2[s * OUT_CH + chan];
    }
    // reduce across the 4 edge slots
    acc += __shfl_xor_sync(0xFFFFFFFFu, acc, 8);
    acc += __shfl_xor_sync(0xFFFFFFFFu, acc, 16);
    den += __shfl_xor_sync(0xFFFFFFFFu, den, 8);
    den += __shfl_xor_sync(0xFFFFFFFFu, den, 16);
    if (lane < OUT_CH) out[w * OUT_CH + lane] = acc / den + b2[lane];
}

// ---------------- launcher ---------------------------------------------------
extern "C" void kernel_launch(void* const* d_in, const int* in_sizes, int n_in,
                              void* d_out, int out_size) {
    const float* x      = (const float*)d_in[0];
    const int*   ei     = (const int*)  d_in[1];   // int32 (JAX x64 disabled)
    const float* W1     = (const float*)d_in[2];
    const float* a_src1 = (const float*)d_in[3];
    const float* a_dst1 = (const float*)d_in[4];
    const float* b1     = (const float*)d_in[5];
    const float* W2     = (const float*)d_in[6];
    const float* a_src2 = (const float*)d_in[7];
    const float* a_dst2 = (const float*)d_in[8];
    const float* b2     = (const float*)d_in[9];
    float*       out    = (float*)      d_out;

    const int N = in_sizes[0] / IN_CH;   // 50000
    const int E = in_sizes[1] / 2;       // 800000

    // side stream + events, created once on the (uncaptured) correctness call
    static cudaStream_t s2 = []() {
        cudaStream_t s; cudaStreamCreateWithFlags(&s, cudaStreamNonBlocking); return s;
    }();
    static cudaEvent_t ev0 = []() {
        cudaEvent_t e; cudaEventCreateWithFlags(&e, cudaEventDisableTiming); return e;
    }();
    static cudaEvent_t ev1 = []() {
        cudaEvent_t e; cudaEventCreateWithFlags(&e, cudaEventDisableTiming); return e;
    }();

    // fork: CSR build on s2, gemm1 on main stream
    cudaEventRecord(ev0, 0);
    cudaStreamWaitEvent(s2, ev0, 0);

    // --- branch A (s2): CSR build ---
    void* deg_ptr = nullptr;
    cudaGetSymbolAddress(&deg_ptr, g_deg);
    cudaMemsetAsync(deg_ptr, 0, N * sizeof(int), s2);
    {
        int nt = (E + 3) / 4;
        k_hist<<<(nt + 255) / 256, 256, 0, s2>>>(ei, E);
    }
    k_scan_part<<<SCAN_BLOCKS, 1024, 0, s2>>>(N);
    k_scan_fill<<<SCAN_BLOCKS, 1024, 0, s2>>>(N);
    {
        int nt = (E + 7) / 8;
        k_scatter<<<(nt + 255) / 256, 256, 0, s2>>>(ei, E);
    }
    cudaEventRecord(ev1, s2);

    // --- branch B (main): layer-1 linear ---
    k_gemm1<<<(N + 15) / 16, 128>>>(x, W1, a_src1, a_dst1, N);

    // join
    cudaStreamWaitEvent(0, ev1, 0);

    // fused layer-1 aggregation + ELU + layer-2 linear
    k_agg1<<<(N * 32 + 255) / 256, 256>>>(b1, W2, a_src2, a_dst2, N);
    // layer-2 aggregation
    k_agg2<<<(N * 32 + 255) / 256, 256>>>(b2, out, N);
}